// round 9
// baseline (speedup 1.0000x reference)
#include <cuda_runtime.h>

#define Hh 126
#define Ww 126
#define WP 128
#define NPIX (Hh*Ww)        // 15876
#define PLANE (Hh*WP)       // 16128
#define NLAYER 6

#define SWZ(b) ((b) ^ (((b) >> 3) & 0x70))

// ping-pong activation buffers + involution weight buffer
__device__ float g_x[64*PLANE];     // ~4.1 MB
__device__ float g_y[64*PLANE];     // ~4.1 MB
__device__ float g_w[196*PLANE];    // ~12.6 MB

// ---------------------------------------------------------------------------
// conv_in: (1,3,128,128) -> (1,64,126,126), 3x3 valid conv
// ---------------------------------------------------------------------------
__global__ __launch_bounds__(256) void k_conv_in(const float* __restrict__ in,
                                                 const float* __restrict__ wt,
                                                 const float* __restrict__ bias,
                                                 float* __restrict__ out)
{
    int t = blockIdx.x * 256 + threadIdx.x;      // over 126*128 padded plane
    int c = blockIdx.y;
    int y = t >> 7, x = t & 127;
    if (y >= Hh || x >= Ww) return;
    float acc = bias[c];
    const float* wc = wt + c * 27;
    #pragma unroll
    for (int i = 0; i < 3; i++)
        #pragma unroll
        for (int r = 0; r < 3; r++)
            #pragma unroll
            for (int s = 0; s < 3; s++)
                acc += wc[(i*3+r)*3+s] * in[(i*128 + (y+r))*128 + (x+s)];
    out[c*PLANE + y*WP + x] = acc;
}

// ---------------------------------------------------------------------------
// kgen v7: 256 threads / 48 pixels, 3 pixels per thread.
// Weights via __ldg (warp-uniform, L1-resident); each weight fetch serves
// 48 FMA in Phase B.
// ---------------------------------------------------------------------------
__global__ __launch_bounds__(256) void k_kgen(const float* __restrict__ src,
    const float* __restrict__ wr, const float* __restrict__ br,
    const float* __restrict__ gmm, const float* __restrict__ bet,
    const float* __restrict__ mu, const float* __restrict__ var,
    const float* __restrict__ ws, const float* __restrict__ bs)
{
    __shared__ alignas(16) float xs2[48*68];     // [p][ic] pad 68
    __shared__ alignas(16) float ts[48*20];      // [p][c] pad 20

    int tid = threadIdx.x;
    int pix0 = blockIdx.x * 48;
    int p = tid & 15;       // pixel slot (handles p, p+16, p+32)
    int c = tid >> 4;       // channel 0..15

    for (int i = tid; i < 3072; i += 256) {
        int ic = i / 48, pp = i - ic*48;
        int px2 = pix0 + pp;
        float v = 0.f;
        if (px2 < NPIX) {
            int y2 = px2 / 126;
            v = src[ic*PLANE + y2*WP + (px2 - y2*126)];
        }
        xs2[pp*68 + ic] = v;
    }
    __syncthreads();

    // Phase A: t(c, p), t(c, p+16), t(c, p+32)
    {
        float a0 = 0.f, a1 = 0.f, a2 = 0.f;
        const float4* wv4 = (const float4*)(wr + c*64);
        #pragma unroll
        for (int i4 = 0; i4 < 16; i4++) {
            float4 wv = __ldg(&wv4[i4]);
            float4 xa = *(const float4*)&xs2[p*68 + i4*4];
            float4 xb = *(const float4*)&xs2[(p+16)*68 + i4*4];
            float4 xc = *(const float4*)&xs2[(p+32)*68 + i4*4];
            a0 += xa.x*wv.x + xa.y*wv.y + xa.z*wv.z + xa.w*wv.w;
            a1 += xb.x*wv.x + xb.y*wv.y + xb.z*wv.z + xb.w*wv.w;
            a2 += xc.x*wv.x + xc.y*wv.y + xc.z*wv.z + xc.w*wv.w;
        }
        float s = __ldg(&gmm[c]) * rsqrtf(__ldg(&var[c]) + 1e-5f);
        float h = (__ldg(&br[c]) - __ldg(&mu[c])) * s + __ldg(&bet[c]);
        ts[p*20 + c]      = fmaxf(a0 * s + h, 0.f);
        ts[(p+16)*20 + c] = fmaxf(a1 * s + h, 0.f);
        ts[(p+32)*20 + c] = fmaxf(a2 * s + h, 0.f);
    }
    __syncthreads();

    // Phase B: j = c, c+16, ... ; 3 pixels per thread
    float tA[16], tB[16], tC[16];
    #pragma unroll
    for (int k = 0; k < 4; k++) {
        float4 va = *(const float4*)&ts[p*20 + k*4];
        tA[k*4] = va.x; tA[k*4+1] = va.y; tA[k*4+2] = va.z; tA[k*4+3] = va.w;
        float4 vb = *(const float4*)&ts[(p+16)*20 + k*4];
        tB[k*4] = vb.x; tB[k*4+1] = vb.y; tB[k*4+2] = vb.z; tB[k*4+3] = vb.w;
        float4 vc = *(const float4*)&ts[(p+32)*20 + k*4];
        tC[k*4] = vc.x; tC[k*4+1] = vc.y; tC[k*4+2] = vc.z; tC[k*4+3] = vc.w;
    }
    int pixA = pix0 + p, pixB = pixA + 16, pixC = pixA + 32;
    bool vA = pixA < NPIX, vB = pixB < NPIX, vC = pixC < NPIX;
    int addrA = 0, addrB = 0, addrC = 0;
    if (vA) { int yy = pixA / 126; addrA = yy*WP + (pixA - yy*126); }
    if (vB) { int yy = pixB / 126; addrB = yy*WP + (pixB - yy*126); }
    if (vC) { int yy = pixC / 126; addrC = yy*WP + (pixC - yy*126); }

    #pragma unroll 1
    for (int j = c; j < 196; j += 16) {
        const float4* wv4 = (const float4*)(ws + j*16);
        float4 w0 = __ldg(&wv4[0]), w1 = __ldg(&wv4[1]);
        float4 w2 = __ldg(&wv4[2]), w3 = __ldg(&wv4[3]);
        float bj = __ldg(&bs[j]);
        float aA = bj, aB = bj, aC = bj;
        aA += w0.x*tA[0]  + w0.y*tA[1]  + w0.z*tA[2]  + w0.w*tA[3];
        aB += w0.x*tB[0]  + w0.y*tB[1]  + w0.z*tB[2]  + w0.w*tB[3];
        aC += w0.x*tC[0]  + w0.y*tC[1]  + w0.z*tC[2]  + w0.w*tC[3];
        aA += w1.x*tA[4]  + w1.y*tA[5]  + w1.z*tA[6]  + w1.w*tA[7];
        aB += w1.x*tB[4]  + w1.y*tB[5]  + w1.z*tB[6]  + w1.w*tB[7];
        aC += w1.x*tC[4]  + w1.y*tC[5]  + w1.z*tC[6]  + w1.w*tC[7];
        aA += w2.x*tA[8]  + w2.y*tA[9]  + w2.z*tA[10] + w2.w*tA[11];
        aB += w2.x*tB[8]  + w2.y*tB[9]  + w2.z*tB[10] + w2.w*tB[11];
        aC += w2.x*tC[8]  + w2.y*tC[9]  + w2.z*tC[10] + w2.w*tC[11];
        aA += w3.x*tA[12] + w3.y*tA[13] + w3.z*tA[14] + w3.w*tA[15];
        aB += w3.x*tB[12] + w3.y*tB[13] + w3.z*tB[14] + w3.w*tB[15];
        aC += w3.x*tC[12] + w3.y*tC[13] + w3.z*tC[14] + w3.w*tC[15];
        if (vA) g_w[j*PLANE + addrA] = aA;
        if (vB) g_w[j*PLANE + addrB] = aB;
        if (vC) g_w[j*PLANE + addrC] = aC;
    }
}

// ---------------------------------------------------------------------------
// agg (round-4 version): 256 threads, 32x16 tile, 8 ch/block,
// 2 px x 8 ch per thread. grid (4, 8, 8).
// ---------------------------------------------------------------------------
#define AGG_ROWS 22
#define AGG_PCH  40
#define AGG_CHUNKS (AGG_ROWS*2*AGG_PCH)

__global__ __launch_bounds__(256) void k_agg(const float* __restrict__ src,
                                             float* __restrict__ dst)
{
    __shared__ alignas(16) float xs[AGG_CHUNKS*4];

    int g    = blockIdx.z >> 1;
    int half = blockIdx.z & 1;
    int x0 = blockIdx.x * 32, y0 = blockIdx.y * 16;
    int tid = threadIdx.x;

    for (int i = tid; i < 8*22*38; i += 256) {
        int c = i / 836; int rem = i - c*836;
        int r = rem / 38; int pp = rem - r*38;
        int gy = y0 + r - 3, gx = x0 + pp - 3;
        float v = 0.f;
        if ((unsigned)gy < 126u && (unsigned)gx < 126u)
            v = src[(g*16 + half*8 + c)*PLANE + gy*WP + gx];
        int chunk = (r*2 + (c >> 2))*AGG_PCH + pp;
        int byte = chunk * 16;
        *(float*)((char*)xs + SWZ(byte) + (c & 3)*4) = v;
    }
    __syncthreads();

    int ty = tid >> 4;            // 0..15
    int xp = (tid & 15) * 2;      // 0,2,...,30
    int gy = y0 + ty;
    if (gy >= 126) return;
    int gx0 = x0 + xp;

    const float* wbase = g_w + (g*49)*PLANE + gy*WP + gx0;

    float acc[8][2];
    #pragma unroll
    for (int cc = 0; cc < 8; cc++) { acc[cc][0] = 0.f; acc[cc][1] = 0.f; }

    #pragma unroll 1
    for (int kh = 0; kh < 7; kh++) {
        float2 wv[7];
        #pragma unroll
        for (int kw = 0; kw < 7; kw++)
            wv[kw] = *(const float2*)(wbase + (kh*7 + kw)*PLANE);

        #pragma unroll
        for (int cg = 0; cg < 2; cg++) {
            int rowbase = ((ty + kh)*2 + cg)*AGG_PCH;
            float4 xq[8];
            #pragma unroll
            for (int j = 0; j < 8; j++) {
                int byte = (rowbase + xp + j) * 16;
                xq[j] = *(const float4*)((const char*)xs + SWZ(byte));
            }
            #pragma unroll
            for (int kw = 0; kw < 7; kw++) {
                #pragma unroll
                for (int q = 0; q < 2; q++) {
                    float w = q ? wv[kw].y : wv[kw].x;
                    float4 xv = xq[q + kw];
                    acc[cg*4+0][q] += w * xv.x;
                    acc[cg*4+1][q] += w * xv.y;
                    acc[cg*4+2][q] += w * xv.z;
                    acc[cg*4+3][q] += w * xv.w;
                }
            }
        }
    }

    #pragma unroll
    for (int cc = 0; cc < 8; cc++) {
        int ch = g*16 + half*8 + cc;
        float* o = dst + ch*PLANE + gy*WP + gx0;
        #pragma unroll
        for (int q = 0; q < 2; q++)
            if (gx0 + q < 126) o[q] = fmaxf(acc[cc][q], 0.f);
    }
}

// ---------------------------------------------------------------------------
// conv_out v4: same tiling as round-4 v2 (2 oc x 16 px per thread) but
// 8-ic weight stages -> 37KB smem -> 4 blocks/SM.
// grid (124 rows, 2 oc-groups), block 256 = 8 colgroups x 32 oc-lanes.
// ---------------------------------------------------------------------------
#define CO_XS (8*3*132)         // 3168 floats
#define CO_WS (64*8*12)         // 6144 floats
#define CO_SMEM ((CO_XS + CO_WS) * 4)

__global__ __launch_bounds__(256) void k_conv_out(const float* __restrict__ src,
    const float* __restrict__ wt, const float* __restrict__ bias,
    float* __restrict__ out)
{
    extern __shared__ float sm[];
    float* xs  = sm;            // [8][3][132] swizzled
    float* wsh = sm + CO_XS;    // [64][8][12]
    int y = blockIdx.x;         // output row 0..123
    int ocg = blockIdx.y;       // 0..1
    int tid = threadIdx.x;
    int cg = tid & 7, ol = tid >> 3;      // ol 0..31
    float accA[16] = {}, accB[16] = {};

    for (int icc = 0; icc < 8; icc++) {
        __syncthreads();
        for (int idx = tid; idx < CO_XS; idx += 256) {
            int ic = idx / 396; int rem = idx - ic*396;
            int r = rem / 132;  int col = rem - r*132;
            float v = 0.f;
            if (col < 126) v = src[(icc*8 + ic)*PLANE + (y + r)*WP + col];
            *(float*)((char*)xs + SWZ(idx*4)) = v;
        }
        for (int idx = tid; idx < CO_WS; idx += 256) {
            int o = idx / 96;  int rem = idx - o*96;
            int ic = rem / 12; int k = rem - ic*12;
            wsh[idx] = (k < 9) ? wt[(ocg*64 + o)*576 + (icc*8 + ic)*9 + k] : 0.f;
        }
        __syncthreads();

        #pragma unroll 1
        for (int ic = 0; ic < 8; ic++) {
            float wA[9], wB[9];
            {
                const float* wb = &wsh[(ol*8 + ic)*12];
                float4 w0 = *(const float4*)wb;
                float4 w1 = *(const float4*)(wb + 4);
                wA[0]=w0.x; wA[1]=w0.y; wA[2]=w0.z; wA[3]=w0.w;
                wA[4]=w1.x; wA[5]=w1.y; wA[6]=w1.z; wA[7]=w1.w;
                wA[8]=wb[8];
                const float* wc = &wsh[((ol+32)*8 + ic)*12];
                float4 v0 = *(const float4*)wc;
                float4 v1 = *(const float4*)(wc + 4);
                wB[0]=v0.x; wB[1]=v0.y; wB[2]=v0.z; wB[3]=v0.w;
                wB[4]=v1.x; wB[5]=v1.y; wB[6]=v1.z; wB[7]=v1.w;
                wB[8]=wc[8];
            }
            #pragma unroll
            for (int kh = 0; kh < 3; kh++) {
                float xr[18];
                int base = ((ic*3 + kh)*132 + cg*16) * 4;   // byte offset
                float4 a0 = *(const float4*)((const char*)xs + SWZ(base));
                float4 a1 = *(const float4*)((const char*)xs + SWZ(base + 16));
                float4 a2 = *(const float4*)((const char*)xs + SWZ(base + 32));
                float4 a3 = *(const float4*)((const char*)xs + SWZ(base + 48));
                float2 a4 = *(const float2*)((const char*)xs + SWZ(base + 64));
                xr[0]=a0.x; xr[1]=a0.y; xr[2]=a0.z; xr[3]=a0.w;
                xr[4]=a1.x; xr[5]=a1.y; xr[6]=a1.z; xr[7]=a1.w;
                xr[8]=a2.x; xr[9]=a2.y; xr[10]=a2.z; xr[11]=a2.w;
                xr[12]=a3.x; xr[13]=a3.y; xr[14]=a3.z; xr[15]=a3.w;
                xr[16]=a4.x; xr[17]=a4.y;
                #pragma unroll
                for (int kw = 0; kw < 3; kw++) {
                    float fa = wA[kh*3 + kw];
                    float fb = wB[kh*3 + kw];
                    #pragma unroll
                    for (int p = 0; p < 16; p++) {
                        accA[p] += fa * xr[p + kw];
                        accB[p] += fb * xr[p + kw];
                    }
                }
            }
        }
    }

    int ocA = ocg*64 + ol, ocB = ocA + 32;
    float bA = bias[ocA], bB = bias[ocB];
    int xbase = cg * 16;
    float* oA = &out[(ocA*124 + y)*124 + xbase];
    float* oB = &out[(ocB*124 + y)*124 + xbase];
    #pragma unroll
    for (int p = 0; p < 16; p++)
        if (xbase + p < 124) { oA[p] = accA[p] + bA; oB[p] = accB[p] + bB; }
}

// ---------------------------------------------------------------------------
extern "C" void kernel_launch(void* const* d_in, const int* in_sizes, int n_in,
                              void* d_out, int out_size)
{
    const float* input = (const float*)d_in[0];
    const float* ciw   = (const float*)d_in[1];
    const float* cib   = (const float*)d_in[2];
    const float* wr    = (const float*)d_in[3];
    const float* brr   = (const float*)d_in[4];
    const float* gmm   = (const float*)d_in[5];
    const float* bet   = (const float*)d_in[6];
    const float* mu    = (const float*)d_in[7];
    const float* var   = (const float*)d_in[8];
    const float* ws    = (const float*)d_in[9];
    const float* bs    = (const float*)d_in[10];
    const float* cow   = (const float*)d_in[11];
    const float* cob   = (const float*)d_in[12];

    float *px, *py;
    cudaGetSymbolAddress((void**)&px, g_x);
    cudaGetSymbolAddress((void**)&py, g_y);
    cudaFuncSetAttribute(k_conv_out, cudaFuncAttributeMaxDynamicSharedMemorySize, CO_SMEM);

    k_conv_in<<<dim3(63, 64), 256>>>(input, ciw, cib, px);

    float* cur = px;
    float* nxt = py;
    for (int l = 0; l < NLAYER; l++) {
        k_kgen<<<331, 256>>>(cur, wr + l*1024, brr + l*16, gmm + l*16, bet + l*16,
                             mu + l*16, var + l*16, ws + l*3136, bs + l*196);
        k_agg<<<dim3(4, 8, 8), 256>>>(cur, nxt);
        float* t = cur; cur = nxt; nxt = t;
    }
    k_conv_out<<<dim3(124, 2), 256, CO_SMEM>>>(cur, cow, cob, (float*)d_out);
}

// round 11
// speedup vs baseline: 1.2322x; 1.2322x over previous
#include <cuda_runtime.h>

#define Hh 126
#define Ww 126
#define WP 128
#define NPIX (Hh*Ww)        // 15876
#define PLANE (Hh*WP)       // 16128
#define NLAYER 6

#define SWZ(b) ((b) ^ (((b) >> 3) & 0x70))

// ping-pong activation buffers + involution weight buffer
__device__ float g_x[64*PLANE];     // ~4.1 MB
__device__ float g_y[64*PLANE];     // ~4.1 MB
__device__ float g_w[196*PLANE];    // ~12.6 MB

// ---------------------------------------------------------------------------
// conv_in: (1,3,128,128) -> (1,64,126,126), 3x3 valid conv
// ---------------------------------------------------------------------------
__global__ __launch_bounds__(256) void k_conv_in(const float* __restrict__ in,
                                                 const float* __restrict__ wt,
                                                 const float* __restrict__ bias,
                                                 float* __restrict__ out)
{
    int t = blockIdx.x * 256 + threadIdx.x;      // over 126*128 padded plane
    int c = blockIdx.y;
    int y = t >> 7, x = t & 127;
    if (y >= Hh || x >= Ww) return;
    float acc = bias[c];
    const float* wc = wt + c * 27;
    #pragma unroll
    for (int i = 0; i < 3; i++)
        #pragma unroll
        for (int r = 0; r < 3; r++)
            #pragma unroll
            for (int s = 0; s < 3; s++)
                acc += wc[(i*3+r)*3+s] * in[(i*128 + (y+r))*128 + (x+s)];
    out[c*PLANE + y*WP + x] = acc;
}

// ---------------------------------------------------------------------------
// kgen v6 (round-8 best): 256 threads / 32 pixels, 2 pixels per thread.
// Weights via __ldg (warp-uniform broadcast, L1-resident).
// ---------------------------------------------------------------------------
__global__ __launch_bounds__(256) void k_kgen(const float* __restrict__ src,
    const float* __restrict__ wr, const float* __restrict__ br,
    const float* __restrict__ gmm, const float* __restrict__ bet,
    const float* __restrict__ mu, const float* __restrict__ var,
    const float* __restrict__ ws, const float* __restrict__ bs)
{
    __shared__ alignas(16) float xs2[32*68];     // [p][ic] pad 68
    __shared__ alignas(16) float ts[32*20];      // [p][c] pad 20

    int tid = threadIdx.x;
    int pix0 = blockIdx.x * 32;
    int p = tid & 15;       // pixel slot (handles p and p+16)
    int c = tid >> 4;       // channel 0..15

    for (int i = tid; i < 2048; i += 256) {
        int ic = i >> 5, pp = i & 31;
        int px2 = pix0 + pp;
        float v = 0.f;
        if (px2 < NPIX) {
            int y2 = px2 / 126;
            v = src[ic*PLANE + y2*WP + (px2 - y2*126)];
        }
        xs2[pp*68 + ic] = v;
    }
    __syncthreads();

    // Phase A: t(c, pA) and t(c, pB)
    {
        float a0 = 0.f, a1 = 0.f;
        const float4* wv4 = (const float4*)(wr + c*64);
        #pragma unroll
        for (int i4 = 0; i4 < 16; i4++) {
            float4 wv = __ldg(&wv4[i4]);
            float4 xa = *(const float4*)&xs2[p*68 + i4*4];
            float4 xb = *(const float4*)&xs2[(p+16)*68 + i4*4];
            a0 += xa.x*wv.x + xa.y*wv.y + xa.z*wv.z + xa.w*wv.w;
            a1 += xb.x*wv.x + xb.y*wv.y + xb.z*wv.z + xb.w*wv.w;
        }
        float s = __ldg(&gmm[c]) * rsqrtf(__ldg(&var[c]) + 1e-5f);
        float h = (__ldg(&br[c]) - __ldg(&mu[c])) * s + __ldg(&bet[c]);
        ts[p*20 + c]      = fmaxf(a0 * s + h, 0.f);
        ts[(p+16)*20 + c] = fmaxf(a1 * s + h, 0.f);
    }
    __syncthreads();

    // Phase B: j = c, c+16, ... ; 2 pixels per thread
    float tA[16], tB[16];
    #pragma unroll
    for (int k = 0; k < 4; k++) {
        float4 va = *(const float4*)&ts[p*20 + k*4];
        tA[k*4] = va.x; tA[k*4+1] = va.y; tA[k*4+2] = va.z; tA[k*4+3] = va.w;
        float4 vb = *(const float4*)&ts[(p+16)*20 + k*4];
        tB[k*4] = vb.x; tB[k*4+1] = vb.y; tB[k*4+2] = vb.z; tB[k*4+3] = vb.w;
    }
    int pixA = pix0 + p, pixB = pix0 + p + 16;
    bool vA = pixA < NPIX, vB = pixB < NPIX;
    int addrA = 0, addrB = 0;
    if (vA) { int yy = pixA / 126; addrA = yy*WP + (pixA - yy*126); }
    if (vB) { int yy = pixB / 126; addrB = yy*WP + (pixB - yy*126); }

    #pragma unroll 1
    for (int j = c; j < 196; j += 16) {
        const float4* wv4 = (const float4*)(ws + j*16);
        float4 w0 = __ldg(&wv4[0]), w1 = __ldg(&wv4[1]);
        float4 w2 = __ldg(&wv4[2]), w3 = __ldg(&wv4[3]);
        float bj = __ldg(&bs[j]);
        float aA = bj, aB = bj;
        aA += w0.x*tA[0]  + w0.y*tA[1]  + w0.z*tA[2]  + w0.w*tA[3];
        aB += w0.x*tB[0]  + w0.y*tB[1]  + w0.z*tB[2]  + w0.w*tB[3];
        aA += w1.x*tA[4]  + w1.y*tA[5]  + w1.z*tA[6]  + w1.w*tA[7];
        aB += w1.x*tB[4]  + w1.y*tB[5]  + w1.z*tB[6]  + w1.w*tB[7];
        aA += w2.x*tA[8]  + w2.y*tA[9]  + w2.z*tA[10] + w2.w*tA[11];
        aB += w2.x*tB[8]  + w2.y*tB[9]  + w2.z*tB[10] + w2.w*tB[11];
        aA += w3.x*tA[12] + w3.y*tA[13] + w3.z*tA[14] + w3.w*tA[15];
        aB += w3.x*tB[12] + w3.y*tB[13] + w3.z*tB[14] + w3.w*tB[15];
        if (vA) g_w[j*PLANE + addrA] = aA;
        if (vB) g_w[j*PLANE + addrB] = aB;
    }
}

// ---------------------------------------------------------------------------
// agg (round-4 version): 256 threads, 32x16 tile, 8 ch/block,
// 2 px x 8 ch per thread. grid (4, 8, 8).
// ---------------------------------------------------------------------------
#define AGG_ROWS 22
#define AGG_PCH  40
#define AGG_CHUNKS (AGG_ROWS*2*AGG_PCH)

__global__ __launch_bounds__(256) void k_agg(const float* __restrict__ src,
                                             float* __restrict__ dst)
{
    __shared__ alignas(16) float xs[AGG_CHUNKS*4];

    int g    = blockIdx.z >> 1;
    int half = blockIdx.z & 1;
    int x0 = blockIdx.x * 32, y0 = blockIdx.y * 16;
    int tid = threadIdx.x;

    for (int i = tid; i < 8*22*38; i += 256) {
        int c = i / 836; int rem = i - c*836;
        int r = rem / 38; int pp = rem - r*38;
        int gy = y0 + r - 3, gx = x0 + pp - 3;
        float v = 0.f;
        if ((unsigned)gy < 126u && (unsigned)gx < 126u)
            v = src[(g*16 + half*8 + c)*PLANE + gy*WP + gx];
        int chunk = (r*2 + (c >> 2))*AGG_PCH + pp;
        int byte = chunk * 16;
        *(float*)((char*)xs + SWZ(byte) + (c & 3)*4) = v;
    }
    __syncthreads();

    int ty = tid >> 4;            // 0..15
    int xp = (tid & 15) * 2;      // 0,2,...,30
    int gy = y0 + ty;
    if (gy >= 126) return;
    int gx0 = x0 + xp;

    const float* wbase = g_w + (g*49)*PLANE + gy*WP + gx0;

    float acc[8][2];
    #pragma unroll
    for (int cc = 0; cc < 8; cc++) { acc[cc][0] = 0.f; acc[cc][1] = 0.f; }

    #pragma unroll 1
    for (int kh = 0; kh < 7; kh++) {
        float2 wv[7];
        #pragma unroll
        for (int kw = 0; kw < 7; kw++)
            wv[kw] = *(const float2*)(wbase + (kh*7 + kw)*PLANE);

        #pragma unroll
        for (int cg = 0; cg < 2; cg++) {
            int rowbase = ((ty + kh)*2 + cg)*AGG_PCH;
            float4 xq[8];
            #pragma unroll
            for (int j = 0; j < 8; j++) {
                int byte = (rowbase + xp + j) * 16;
                xq[j] = *(const float4*)((const char*)xs + SWZ(byte));
            }
            #pragma unroll
            for (int kw = 0; kw < 7; kw++) {
                #pragma unroll
                for (int q = 0; q < 2; q++) {
                    float w = q ? wv[kw].y : wv[kw].x;
                    float4 xv = xq[q + kw];
                    acc[cg*4+0][q] += w * xv.x;
                    acc[cg*4+1][q] += w * xv.y;
                    acc[cg*4+2][q] += w * xv.z;
                    acc[cg*4+3][q] += w * xv.w;
                }
            }
        }
    }

    #pragma unroll
    for (int cc = 0; cc < 8; cc++) {
        int ch = g*16 + half*8 + cc;
        float* o = dst + ch*PLANE + gy*WP + gx0;
        #pragma unroll
        for (int q = 0; q < 2; q++)
            if (gx0 + q < 126) o[q] = fmaxf(acc[cc][q], 0.f);
    }
}

// ---------------------------------------------------------------------------
// conv_out v4 (round-9, kept — saved ~20us): 8-ic weight stages, 37KB smem,
// grid (124 rows, 2 oc-groups), block 256 = 8 colgroups x 32 oc-lanes,
// 2 oc x 16 px per thread. xs swizzled.
// ---------------------------------------------------------------------------
#define CO_XS (8*3*132)         // 3168 floats
#define CO_WS (64*8*12)         // 6144 floats
#define CO_SMEM ((CO_XS + CO_WS) * 4)

__global__ __launch_bounds__(256) void k_conv_out(const float* __restrict__ src,
    const float* __restrict__ wt, const float* __restrict__ bias,
    float* __restrict__ out)
{
    extern __shared__ float sm[];
    float* xs  = sm;            // [8][3][132] swizzled
    float* wsh = sm + CO_XS;    // [64][8][12]
    int y = blockIdx.x;         // output row 0..123
    int ocg = blockIdx.y;       // 0..1
    int tid = threadIdx.x;
    int cg = tid & 7, ol = tid >> 3;      // ol 0..31
    float accA[16] = {}, accB[16] = {};

    for (int icc = 0; icc < 8; icc++) {
        __syncthreads();
        for (int idx = tid; idx < CO_XS; idx += 256) {
            int ic = idx / 396; int rem = idx - ic*396;
            int r = rem / 132;  int col = rem - r*132;
            float v = 0.f;
            if (col < 126) v = src[(icc*8 + ic)*PLANE + (y + r)*WP + col];
            *(float*)((char*)xs + SWZ(idx*4)) = v;
        }
        for (int idx = tid; idx < CO_WS; idx += 256) {
            int o = idx / 96;  int rem = idx - o*96;
            int ic = rem / 12; int k = rem - ic*12;
            wsh[idx] = (k < 9) ? wt[(ocg*64 + o)*576 + (icc*8 + ic)*9 + k] : 0.f;
        }
        __syncthreads();

        #pragma unroll 1
        for (int ic = 0; ic < 8; ic++) {
            float wA[9], wB[9];
            {
                const float* wb = &wsh[(ol*8 + ic)*12];
                float4 w0 = *(const float4*)wb;
                float4 w1 = *(const float4*)(wb + 4);
                wA[0]=w0.x; wA[1]=w0.y; wA[2]=w0.z; wA[3]=w0.w;
                wA[4]=w1.x; wA[5]=w1.y; wA[6]=w1.z; wA[7]=w1.w;
                wA[8]=wb[8];
                const float* wc = &wsh[((ol+32)*8 + ic)*12];
                float4 v0 = *(const float4*)wc;
                float4 v1 = *(const float4*)(wc + 4);
                wB[0]=v0.x; wB[1]=v0.y; wB[2]=v0.z; wB[3]=v0.w;
                wB[4]=v1.x; wB[5]=v1.y; wB[6]=v1.z; wB[7]=v1.w;
                wB[8]=wc[8];
            }
            #pragma unroll
            for (int kh = 0; kh < 3; kh++) {
                float xr[18];
                int base = ((ic*3 + kh)*132 + cg*16) * 4;   // byte offset
                float4 a0 = *(const float4*)((const char*)xs + SWZ(base));
                float4 a1 = *(const float4*)((const char*)xs + SWZ(base + 16));
                float4 a2 = *(const float4*)((const char*)xs + SWZ(base + 32));
                float4 a3 = *(const float4*)((const char*)xs + SWZ(base + 48));
                float2 a4 = *(const float2*)((const char*)xs + SWZ(base + 64));
                xr[0]=a0.x; xr[1]=a0.y; xr[2]=a0.z; xr[3]=a0.w;
                xr[4]=a1.x; xr[5]=a1.y; xr[6]=a1.z; xr[7]=a1.w;
                xr[8]=a2.x; xr[9]=a2.y; xr[10]=a2.z; xr[11]=a2.w;
                xr[12]=a3.x; xr[13]=a3.y; xr[14]=a3.z; xr[15]=a3.w;
                xr[16]=a4.x; xr[17]=a4.y;
                #pragma unroll
                for (int kw = 0; kw < 3; kw++) {
                    float fa = wA[kh*3 + kw];
                    float fb = wB[kh*3 + kw];
                    #pragma unroll
                    for (int p = 0; p < 16; p++) {
                        accA[p] += fa * xr[p + kw];
                        accB[p] += fb * xr[p + kw];
                    }
                }
            }
        }
    }

    int ocA = ocg*64 + ol, ocB = ocA + 32;
    float bA = bias[ocA], bB = bias[ocB];
    int xbase = cg * 16;
    float* oA = &out[(ocA*124 + y)*124 + xbase];
    float* oB = &out[(ocB*124 + y)*124 + xbase];
    #pragma unroll
    for (int p = 0; p < 16; p++)
        if (xbase + p < 124) { oA[p] = accA[p] + bA; oB[p] = accB[p] + bB; }
}

// ---------------------------------------------------------------------------
extern "C" void kernel_launch(void* const* d_in, const int* in_sizes, int n_in,
                              void* d_out, int out_size)
{
    const float* input = (const float*)d_in[0];
    const float* ciw   = (const float*)d_in[1];
    const float* cib   = (const float*)d_in[2];
    const float* wr    = (const float*)d_in[3];
    const float* brr   = (const float*)d_in[4];
    const float* gmm   = (const float*)d_in[5];
    const float* bet   = (const float*)d_in[6];
    const float* mu    = (const float*)d_in[7];
    const float* var   = (const float*)d_in[8];
    const float* ws    = (const float*)d_in[9];
    const float* bs    = (const float*)d_in[10];
    const float* cow   = (const float*)d_in[11];
    const float* cob   = (const float*)d_in[12];

    float *px, *py;
    cudaGetSymbolAddress((void**)&px, g_x);
    cudaGetSymbolAddress((void**)&py, g_y);
    cudaFuncSetAttribute(k_conv_out, cudaFuncAttributeMaxDynamicSharedMemorySize, CO_SMEM);

    k_conv_in<<<dim3(63, 64), 256>>>(input, ciw, cib, px);

    float* cur = px;
    float* nxt = py;
    for (int l = 0; l < NLAYER; l++) {
        k_kgen<<<497, 256>>>(cur, wr + l*1024, brr + l*16, gmm + l*16, bet + l*16,
                             mu + l*16, var + l*16, ws + l*3136, bs + l*196);
        k_agg<<<dim3(4, 8, 8), 256>>>(cur, nxt);
        float* t = cur; cur = nxt; nxt = t;
    }
    k_conv_out<<<dim3(124, 2), 256, CO_SMEM>>>(cur, cow, cob, (float*)d_out);
}

// round 13
// speedup vs baseline: 1.6655x; 1.3517x over previous
#include <cuda_runtime.h>
#include <cuda_bf16.h>
#include <cstdint>

#define Hh 126
#define Ww 126
#define WP 128
#define NPIX (Hh*Ww)        // 15876
#define PLANE (Hh*WP)       // 16128
#define NLAYER 6

#define SWZ(b) ((b) ^ (((b) >> 3) & 0x70))

// ping-pong activation buffers + involution weight buffer
__device__ float g_x[64*PLANE];     // ~4.1 MB
__device__ float g_y[64*PLANE];     // ~4.1 MB
__device__ float g_w[196*PLANE];    // ~12.6 MB
// pre-swizzled hi/lo bf16 conv_out weights: per shift s: [128 oc][64 ic],
// 16KB image with SW128 swizzle baked in
__device__ __nv_bfloat16 g_wth[9*8192];
__device__ __nv_bfloat16 g_wtl[9*8192];

__device__ __forceinline__ uint32_t smem_u32(const void* p) {
    uint32_t a;
    asm("{ .reg .u64 t; cvta.to.shared.u64 t, %1; cvt.u32.u64 %0, t; }"
        : "=r"(a) : "l"(p));
    return a;
}
__device__ __forceinline__ void ldm_x4(uint32_t* r, uint32_t addr) {
    asm volatile("ldmatrix.sync.aligned.m8n8.x4.shared.b16 {%0,%1,%2,%3}, [%4];"
        : "=r"(r[0]), "=r"(r[1]), "=r"(r[2]), "=r"(r[3]) : "r"(addr));
}
__device__ __forceinline__ void mma_bf16(float* d, const uint32_t* a, const uint32_t* b) {
    asm volatile(
        "mma.sync.aligned.m16n8k16.row.col.f32.bf16.bf16.f32 "
        "{%0,%1,%2,%3}, {%4,%5,%6,%7}, {%8,%9}, {%0,%1,%2,%3};"
        : "+f"(d[0]), "+f"(d[1]), "+f"(d[2]), "+f"(d[3])
        : "r"(a[0]), "r"(a[1]), "r"(a[2]), "r"(a[3]), "r"(b[0]), "r"(b[1]));
}

// ---------------------------------------------------------------------------
// conv_in: (1,3,128,128) -> (1,64,126,126), 3x3 valid conv
// ---------------------------------------------------------------------------
__global__ __launch_bounds__(256) void k_conv_in(const float* __restrict__ in,
                                                 const float* __restrict__ wt,
                                                 const float* __restrict__ bias,
                                                 float* __restrict__ out)
{
    int t = blockIdx.x * 256 + threadIdx.x;
    int c = blockIdx.y;
    int y = t >> 7, x = t & 127;
    if (y >= Hh || x >= Ww) return;
    float acc = bias[c];
    const float* wc = wt + c * 27;
    #pragma unroll
    for (int i = 0; i < 3; i++)
        #pragma unroll
        for (int r = 0; r < 3; r++)
            #pragma unroll
            for (int s = 0; s < 3; s++)
                acc += wc[(i*3+r)*3+s] * in[(i*128 + (y+r))*128 + (x+s)];
    out[c*PLANE + y*WP + x] = acc;
}

// ---------------------------------------------------------------------------
// kgen v6 (best): 256 threads / 32 pixels, 2 pixels per thread.
// ---------------------------------------------------------------------------
__global__ __launch_bounds__(256) void k_kgen(const float* __restrict__ src,
    const float* __restrict__ wr, const float* __restrict__ br,
    const float* __restrict__ gmm, const float* __restrict__ bet,
    const float* __restrict__ mu, const float* __restrict__ var,
    const float* __restrict__ ws, const float* __restrict__ bs)
{
    __shared__ alignas(16) float xs2[32*68];
    __shared__ alignas(16) float ts[32*20];

    int tid = threadIdx.x;
    int pix0 = blockIdx.x * 32;
    int p = tid & 15;
    int c = tid >> 4;

    for (int i = tid; i < 2048; i += 256) {
        int ic = i >> 5, pp = i & 31;
        int px2 = pix0 + pp;
        float v = 0.f;
        if (px2 < NPIX) {
            int y2 = px2 / 126;
            v = src[ic*PLANE + y2*WP + (px2 - y2*126)];
        }
        xs2[pp*68 + ic] = v;
    }
    __syncthreads();

    {
        float a0 = 0.f, a1 = 0.f;
        const float4* wv4 = (const float4*)(wr + c*64);
        #pragma unroll
        for (int i4 = 0; i4 < 16; i4++) {
            float4 wv = __ldg(&wv4[i4]);
            float4 xa = *(const float4*)&xs2[p*68 + i4*4];
            float4 xb = *(const float4*)&xs2[(p+16)*68 + i4*4];
            a0 += xa.x*wv.x + xa.y*wv.y + xa.z*wv.z + xa.w*wv.w;
            a1 += xb.x*wv.x + xb.y*wv.y + xb.z*wv.z + xb.w*wv.w;
        }
        float s = __ldg(&gmm[c]) * rsqrtf(__ldg(&var[c]) + 1e-5f);
        float h = (__ldg(&br[c]) - __ldg(&mu[c])) * s + __ldg(&bet[c]);
        ts[p*20 + c]      = fmaxf(a0 * s + h, 0.f);
        ts[(p+16)*20 + c] = fmaxf(a1 * s + h, 0.f);
    }
    __syncthreads();

    float tA[16], tB[16];
    #pragma unroll
    for (int k = 0; k < 4; k++) {
        float4 va = *(const float4*)&ts[p*20 + k*4];
        tA[k*4] = va.x; tA[k*4+1] = va.y; tA[k*4+2] = va.z; tA[k*4+3] = va.w;
        float4 vb = *(const float4*)&ts[(p+16)*20 + k*4];
        tB[k*4] = vb.x; tB[k*4+1] = vb.y; tB[k*4+2] = vb.z; tB[k*4+3] = vb.w;
    }
    int pixA = pix0 + p, pixB = pix0 + p + 16;
    bool vA = pixA < NPIX, vB = pixB < NPIX;
    int addrA = 0, addrB = 0;
    if (vA) { int yy = pixA / 126; addrA = yy*WP + (pixA - yy*126); }
    if (vB) { int yy = pixB / 126; addrB = yy*WP + (pixB - yy*126); }

    #pragma unroll 1
    for (int j = c; j < 196; j += 16) {
        const float4* wv4 = (const float4*)(ws + j*16);
        float4 w0 = __ldg(&wv4[0]), w1 = __ldg(&wv4[1]);
        float4 w2 = __ldg(&wv4[2]), w3 = __ldg(&wv4[3]);
        float bj = __ldg(&bs[j]);
        float aA = bj, aB = bj;
        aA += w0.x*tA[0]  + w0.y*tA[1]  + w0.z*tA[2]  + w0.w*tA[3];
        aB += w0.x*tB[0]  + w0.y*tB[1]  + w0.z*tB[2]  + w0.w*tB[3];
        aA += w1.x*tA[4]  + w1.y*tA[5]  + w1.z*tA[6]  + w1.w*tA[7];
        aB += w1.x*tB[4]  + w1.y*tB[5]  + w1.z*tB[6]  + w1.w*tB[7];
        aA += w2.x*tA[8]  + w2.y*tA[9]  + w2.z*tA[10] + w2.w*tA[11];
        aB += w2.x*tB[8]  + w2.y*tB[9]  + w2.z*tB[10] + w2.w*tB[11];
        aA += w3.x*tA[12] + w3.y*tA[13] + w3.z*tA[14] + w3.w*tA[15];
        aB += w3.x*tB[12] + w3.y*tB[13] + w3.z*tB[14] + w3.w*tB[15];
        if (vA) g_w[j*PLANE + addrA] = aA;
        if (vB) g_w[j*PLANE + addrB] = aB;
    }
}

// ---------------------------------------------------------------------------
// agg (round-4 version)
// ---------------------------------------------------------------------------
#define AGG_ROWS 22
#define AGG_PCH  40
#define AGG_CHUNKS (AGG_ROWS*2*AGG_PCH)

__global__ __launch_bounds__(256) void k_agg(const float* __restrict__ src,
                                             float* __restrict__ dst)
{
    __shared__ alignas(16) float xs[AGG_CHUNKS*4];

    int g    = blockIdx.z >> 1;
    int half = blockIdx.z & 1;
    int x0 = blockIdx.x * 32, y0 = blockIdx.y * 16;
    int tid = threadIdx.x;

    for (int i = tid; i < 8*22*38; i += 256) {
        int c = i / 836; int rem = i - c*836;
        int r = rem / 38; int pp = rem - r*38;
        int gy = y0 + r - 3, gx = x0 + pp - 3;
        float v = 0.f;
        if ((unsigned)gy < 126u && (unsigned)gx < 126u)
            v = src[(g*16 + half*8 + c)*PLANE + gy*WP + gx];
        int chunk = (r*2 + (c >> 2))*AGG_PCH + pp;
        int byte = chunk * 16;
        *(float*)((char*)xs + SWZ(byte) + (c & 3)*4) = v;
    }
    __syncthreads();

    int ty = tid >> 4;
    int xp = (tid & 15) * 2;
    int gy = y0 + ty;
    if (gy >= 126) return;
    int gx0 = x0 + xp;

    const float* wbase = g_w + (g*49)*PLANE + gy*WP + gx0;

    float acc[8][2];
    #pragma unroll
    for (int cc = 0; cc < 8; cc++) { acc[cc][0] = 0.f; acc[cc][1] = 0.f; }

    #pragma unroll 1
    for (int kh = 0; kh < 7; kh++) {
        float2 wv[7];
        #pragma unroll
        for (int kw = 0; kw < 7; kw++)
            wv[kw] = *(const float2*)(wbase + (kh*7 + kw)*PLANE);

        #pragma unroll
        for (int cg = 0; cg < 2; cg++) {
            int rowbase = ((ty + kh)*2 + cg)*AGG_PCH;
            float4 xq[8];
            #pragma unroll
            for (int j = 0; j < 8; j++) {
                int byte = (rowbase + xp + j) * 16;
                xq[j] = *(const float4*)((const char*)xs + SWZ(byte));
            }
            #pragma unroll
            for (int kw = 0; kw < 7; kw++) {
                #pragma unroll
                for (int q = 0; q < 2; q++) {
                    float w = q ? wv[kw].y : wv[kw].x;
                    float4 xv = xq[q + kw];
                    acc[cg*4+0][q] += w * xv.x;
                    acc[cg*4+1][q] += w * xv.y;
                    acc[cg*4+2][q] += w * xv.z;
                    acc[cg*4+3][q] += w * xv.w;
                }
            }
        }
    }

    #pragma unroll
    for (int cc = 0; cc < 8; cc++) {
        int ch = g*16 + half*8 + cc;
        float* o = dst + ch*PLANE + gy*WP + gx0;
        #pragma unroll
        for (int q = 0; q < 2; q++)
            if (gx0 + q < 126) o[q] = fmaxf(acc[cc][q], 0.f);
    }
}

// ---------------------------------------------------------------------------
// wprep: transpose + hi/lo split + SW128-swizzle conv_out weights.
// g_wth/g_wtl[s]: 16KB = [128 oc rows][64 ic bf16 = 128B], swizzled.
// ---------------------------------------------------------------------------
__global__ __launch_bounds__(256) void k_wprep(const float* __restrict__ cow)
{
    int idx = blockIdx.x * 256 + threadIdx.x;     // 9*128*64 = 73728
    if (idx >= 73728) return;
    int ic = idx & 63;
    int oc = (idx >> 6) & 127;
    int s  = idx >> 13;
    int kh = s / 3, kw = s - kh*3;
    float w = cow[oc*576 + ic*9 + kh*3 + kw];
    __nv_bfloat16 h = __float2bfloat16(w);
    __nv_bfloat16 l = __float2bfloat16(w - __bfloat162float(h));
    int off = SWZ(oc*128 + ic*2) >> 1;            // element offset
    g_wth[s*8192 + off] = h;
    g_wtl[s*8192 + off] = l;
}

// ---------------------------------------------------------------------------
// conv_out_mma: bf16 hi/lo implicit GEMM on the classic tensor path
// (ldmatrix + mma.sync.m16n8k16 — compiles under compute_103).
// Block: one output row y, 64 px (x0..x0+63) x 128 oc. 256 thr = 8 warps,
// warp tile 16 px x 64 oc = 8 m16n8 accum frags.
// A = patches [col][ic] hi/lo bf16 in swizzled smem (kh/kw = address offset).
// B = pre-swizzled weights [oc][ic], 16KB raw copy per shift.
// 9 shifts x 3 passes (AhBh, AhBl, AlBh) x 4 k16 x 8 mma.
// ---------------------------------------------------------------------------
#define CO_SMEM 90112

__global__ __launch_bounds__(256) void k_conv_out_mma(const float* __restrict__ src,
    const float* __restrict__ bias, float* __restrict__ out)
{
    extern __shared__ char dsm[];
    uint32_t base = smem_u32(dsm);
    uint32_t Th = (base + 1023) & ~1023u;
    uint32_t Tl = Th + 27648;                 // 3*72*128 bytes each
    uint32_t Wh = Tl + 27648;
    uint32_t Wl = Wh + 16384;
    char* Th_p = dsm + (Th - base);
    char* Tl_p = dsm + (Tl - base);
    char* Wh_p = dsm + (Wh - base);
    char* Wl_p = dsm + (Wl - base);

    int tid = threadIdx.x;
    int lane = tid & 31, w = tid >> 5;
    int y  = blockIdx.x;                      // output row 0..123
    int x0 = blockIdx.y * 64;
    int pxb = (w & 3) * 16;
    int ocb = (w >> 2) * 64;

    // ---- stage X rows y..y+2 as [v][col][ic] hi/lo bf16, swizzled ----
    for (int i = tid; i < 3*32*66; i += 256) {
        int col = i % 66;
        int rest = i / 66;
        int icp = rest & 31;                  // ic pair 0..31
        int v = rest >> 5;                    // 0..2
        int gcol = x0 + col;
        float f0 = 0.f, f1 = 0.f;
        if (gcol < WP) {
            const float* pp = src + (2*icp)*PLANE + (y+v)*WP + gcol;
            f0 = __ldg(pp);
            f1 = __ldg(pp + PLANE);
        }
        __nv_bfloat16 h0 = __float2bfloat16(f0);
        __nv_bfloat16 h1 = __float2bfloat16(f1);
        __nv_bfloat16 l0 = __float2bfloat16(f0 - __bfloat162float(h0));
        __nv_bfloat16 l1 = __float2bfloat16(f1 - __bfloat162float(h1));
        uint32_t hu = (uint32_t)__bfloat16_as_ushort(h0)
                    | ((uint32_t)__bfloat16_as_ushort(h1) << 16);
        uint32_t lu = (uint32_t)__bfloat16_as_ushort(l0)
                    | ((uint32_t)__bfloat16_as_ushort(l1) << 16);
        uint32_t off = SWZ((uint32_t)((v*72 + col)*128 + icp*4));
        *(uint32_t*)(Th_p + off) = hu;
        *(uint32_t*)(Tl_p + off) = lu;
    }

    // ldmatrix per-thread address components
    int aRow  = lane & 15;
    int aHalf = (lane >> 4) * 8;              // halves
    int bRow  = (lane & 7) + ((lane >> 4) << 3);
    int bHalf = ((lane >> 3) & 1) * 8;

    float acc[8][4];
    #pragma unroll
    for (int j = 0; j < 8; j++)
        #pragma unroll
        for (int q = 0; q < 4; q++) acc[j][q] = 0.f;

    #pragma unroll 1
    for (int s = 0; s < 9; s++) {
        int kh = s / 3, kw = s - kh*3;
        __syncthreads();
        {
            const uint4* sh = (const uint4*)(g_wth + s*8192);
            const uint4* sl = (const uint4*)(g_wtl + s*8192);
            uint4* dh = (uint4*)Wh_p;
            uint4* dl = (uint4*)Wl_p;
            #pragma unroll
            for (int i = 0; i < 4; i++) {
                dh[tid + i*256] = __ldg(&sh[tid + i*256]);
                dl[tid + i*256] = __ldg(&sl[tid + i*256]);
            }
        }
        __syncthreads();

        int cA = pxb + aRow + kw;
        uint32_t arow = (uint32_t)((kh*72 + cA)*128);

        #pragma unroll 1
        for (int pass = 0; pass < 3; pass++) {
            uint32_t Ab = (pass == 2) ? Tl : Th;
            uint32_t Bb = (pass == 1) ? Wl : Wh;
            #pragma unroll
            for (int kk = 0; kk < 4; kk++) {
                uint32_t a[4];
                ldm_x4(a, Ab + SWZ(arow + (uint32_t)((kk*16 + aHalf)*2)));
                #pragma unroll
                for (int j = 0; j < 4; j++) {
                    uint32_t b[4];
                    uint32_t boff = (uint32_t)((ocb + j*16 + bRow)*128
                                              + (kk*16 + bHalf)*2);
                    ldm_x4(b, Bb + SWZ(boff));
                    mma_bf16(acc[2*j],     a, b);
                    mma_bf16(acc[2*j + 1], a, b + 2);
                }
            }
        }
    }

    // ---- store: D[m=px][n=oc] fragments, add bias ----
    int r0 = lane >> 2;
    int nc = (lane & 3) * 2;
    int x1 = x0 + pxb + r0;
    int x2 = x1 + 8;
    #pragma unroll
    for (int j = 0; j < 8; j++) {
        int oc = ocb + j*8 + nc;
        float b0 = __ldg(bias + oc), b1 = __ldg(bias + oc + 1);
        if (x1 < 124) {
            out[(oc*124 + y)*124 + x1]       = acc[j][0] + b0;
            out[((oc+1)*124 + y)*124 + x1]   = acc[j][1] + b1;
        }
        if (x2 < 124) {
            out[(oc*124 + y)*124 + x2]       = acc[j][2] + b0;
            out[((oc+1)*124 + y)*124 + x2]   = acc[j][3] + b1;
        }
    }
}

// ---------------------------------------------------------------------------
extern "C" void kernel_launch(void* const* d_in, const int* in_sizes, int n_in,
                              void* d_out, int out_size)
{
    const float* input = (const float*)d_in[0];
    const float* ciw   = (const float*)d_in[1];
    const float* cib   = (const float*)d_in[2];
    const float* wr    = (const float*)d_in[3];
    const float* brr   = (const float*)d_in[4];
    const float* gmm   = (const float*)d_in[5];
    const float* bet   = (const float*)d_in[6];
    const float* mu    = (const float*)d_in[7];
    const float* var   = (const float*)d_in[8];
    const float* ws    = (const float*)d_in[9];
    const float* bs    = (const float*)d_in[10];
    const float* cow   = (const float*)d_in[11];
    const float* cob   = (const float*)d_in[12];

    float *px, *py;
    cudaGetSymbolAddress((void**)&px, g_x);
    cudaGetSymbolAddress((void**)&py, g_y);
    cudaFuncSetAttribute(k_conv_out_mma,
                         cudaFuncAttributeMaxDynamicSharedMemorySize, CO_SMEM);

    k_wprep<<<288, 256>>>(cow);
    k_conv_in<<<dim3(63, 64), 256>>>(input, ciw, cib, px);

    float* cur = px;
    float* nxt = py;
    for (int l = 0; l < NLAYER; l++) {
        k_kgen<<<497, 256>>>(cur, wr + l*1024, brr + l*16, gmm + l*16, bet + l*16,
                             mu + l*16, var + l*16, ws + l*3136, bs + l*196);
        k_agg<<<dim3(4, 8, 8), 256>>>(cur, nxt);
        float* t = cur; cur = nxt; nxt = t;
    }
    k_conv_out_mma<<<dim3(124, 2), 256, CO_SMEM>>>(cur, cob, (float*)d_out);
}